// round 1
// baseline (speedup 1.0000x reference)
#include <cuda_runtime.h>

// FourierELU: along axis 2 (size 8) of x[32,64,8,64,64]:
//   rfft(8) -> pad to 9 bins -> irfft(16) -> elu -> rfft(16) -> keep 5 bins -> irfft(8)
// Entire chain is y = B * elu(A * x) with fixed 16x8 / 8x16 matrices.
// Closed form (derived & verified analytically):
//   alt        = sum_n (-1)^n x[n]
//   xup[2m]    = 0.5*x[m] + (-1)^m * alt/16
//   xup[2t+1]  = sum_n d[(t-n)&7] * x[n]           (8-pt circulant, d[r]=d[7-r])
//   y[m]       = elu(xup[2m]) + sum_t e[(m-t)&7] * elu(xup[2t+1]),  e[s]=2*d[(s-1)&7]

#define PLANE4  1024            // (64*64)/4 float4 per plane
#define OUTER   2048            // 32*64
#define TOTAL4  (OUTER * PLANE4)
#define NTHREADS 256

__device__ __forceinline__ float eluf(float v) {
    return v > 0.0f ? v : (__expf(v) - 1.0f);
}

__device__ __forceinline__ float4 f4elu(float4 v) {
    return make_float4(eluf(v.x), eluf(v.y), eluf(v.z), eluf(v.w));
}

__device__ __forceinline__ float4 f4fma(float a, float4 b, float4 c) {
    return make_float4(fmaf(a, b.x, c.x), fmaf(a, b.y, c.y),
                       fmaf(a, b.z, c.z), fmaf(a, b.w, c.w));
}

__device__ __forceinline__ float4 f4scale(float a, float4 b) {
    return make_float4(a * b.x, a * b.y, a * b.z, a * b.w);
}

__device__ __forceinline__ float4 f4add(float4 a, float4 b) {
    return make_float4(a.x + b.x, a.y + b.y, a.z + b.z, a.w + b.w);
}

__device__ __forceinline__ float4 f4sub(float4 a, float4 b) {
    return make_float4(a.x - b.x, a.y - b.y, a.z - b.z, a.w - b.w);
}

__global__ void __launch_bounds__(NTHREADS, 2)
fourier_elu_kernel(const float4* __restrict__ in, float4* __restrict__ out) {
    const int tid   = blockIdx.x * NTHREADS + threadIdx.x;   // 0 .. TOTAL4-1
    const int outer = tid >> 10;          // which (b,c) plane-group
    const int inner = tid & 1023;         // float4 index within 64x64 plane
    const int base  = outer * (8 * PLANE4) + inner;

    // Circulant kernel d[r] (r = 0..7), d[r] = d[7-r]:
    const float D0 =  0.31420871834f;
    const float D1 = -0.09353786017f;
    const float D2 =  0.04176116486f;
    const float D3 = -0.01243202296f;
    const float DD[8] = { D0, D1, D2, D3, D3, D2, D1, D0 };
    // Output mix e[s] = 2*d[(s-1)&7]:
    const float EE[8] = { 2.0f*D0, 2.0f*D0, 2.0f*D1, 2.0f*D2,
                          2.0f*D3, 2.0f*D3, 2.0f*D2, 2.0f*D1 };

    // Load 8 group samples (each a float4 of 4 adjacent pixels), fully coalesced.
    float4 xv[8];
#pragma unroll
    for (int g = 0; g < 8; g++) {
        xv[g] = in[base + g * PLANE4];
    }

    // Alternating sum (Nyquist term).
    float4 alt = f4add(f4add(f4sub(xv[0], xv[1]), f4sub(xv[2], xv[3])),
                       f4add(f4sub(xv[4], xv[5]), f4sub(xv[6], xv[7])));
    float4 ap = f4scale(0.0625f, alt);
    float4 an = make_float4(-ap.x, -ap.y, -ap.z, -ap.w);

    // y[m] accumulators, initialized with elu(even upsample) (identity path of B).
    float4 acc[8];
#pragma unroll
    for (int m = 0; m < 8; m++) {
        acc[m] = f4elu(f4fma(0.5f, xv[m], (m & 1) ? an : ap));
    }

    // Odd upsamples: circulant, elu, then scatter into all outputs via e[].
#pragma unroll
    for (int t = 0; t < 8; t++) {
        float4 s = f4scale(DD[t & 7], xv[0]);
#pragma unroll
        for (int n = 1; n < 8; n++) {
            s = f4fma(DD[(t - n) & 7], xv[n], s);
        }
        s = f4elu(s);
#pragma unroll
        for (int m = 0; m < 8; m++) {
            acc[m] = f4fma(EE[(m - t) & 7], s, acc[m]);
        }
    }

#pragma unroll
    for (int g = 0; g < 8; g++) {
        out[base + g * PLANE4] = acc[g];
    }
}

extern "C" void kernel_launch(void* const* d_in, const int* in_sizes, int n_in,
                              void* d_out, int out_size) {
    (void)in_sizes; (void)n_in; (void)out_size;
    const float4* in4  = reinterpret_cast<const float4*>(d_in[0]);
    float4*       out4 = reinterpret_cast<float4*>(d_out);
    fourier_elu_kernel<<<TOTAL4 / NTHREADS, NTHREADS>>>(in4, out4);
}

// round 2
// speedup vs baseline: 1.0517x; 1.0517x over previous
#include <cuda_runtime.h>

// FourierELU on x[32,64,8,64,64], axis 2 (size 8):
//   rfft(8) -> pad to 9 bins -> irfft(16) -> elu -> rfft(16) -> keep 5 -> irfft(8)
// Closed form: y = B * elu(A * x):
//   alt        = sum_n (-1)^n x[n]
//   xup[2m]    = 0.5*x[m] + (-1)^m * alt/16
//   xup[2t+1]  = sum_n d[(t-n)&7] * x[n]          (8-pt symmetric circulant)
//   y[m]       = elu(xup[2m]) + sum_t e[(m-t)&7] * elu(xup[2t+1]), e[s]=2*d[(s-1)&7]
//
// R2: all linear chains in packed f32x2 (SASS FFMA2) to halve FMA issue slots.

#define PLANE4  1024            // (64*64)/4 float4 per plane
#define OUTER   2048            // 32*64
#define TOTAL4  (OUTER * PLANE4)
#define NTHREADS 256

typedef unsigned long long u64;

__device__ __forceinline__ u64 bc(float f) {       // broadcast float into both f32x2 lanes
    unsigned u = __float_as_uint(f);
    return ((u64)u << 32) | (u64)u;
}

__device__ __forceinline__ u64 f2fma(u64 a, u64 b, u64 c) {
    u64 d;
    asm("fma.rn.f32x2 %0, %1, %2, %3;" : "=l"(d) : "l"(a), "l"(b), "l"(c));
    return d;
}
__device__ __forceinline__ u64 f2mul(u64 a, u64 b) {
    u64 d;
    asm("mul.rn.f32x2 %0, %1, %2;" : "=l"(d) : "l"(a), "l"(b));
    return d;
}
__device__ __forceinline__ u64 f2add(u64 a, u64 b) {
    u64 d;
    asm("add.rn.f32x2 %0, %1, %2;" : "=l"(d) : "l"(a), "l"(b));
    return d;
}

__device__ __forceinline__ float eluf(float v) {
    return v > 0.0f ? v : (__expf(v) - 1.0f);
}

__device__ __forceinline__ u64 elu2(u64 v) {
    float a, b;
    asm("mov.b64 {%0, %1}, %2;" : "=f"(a), "=f"(b) : "l"(v));
    a = eluf(a);
    b = eluf(b);
    u64 r;
    asm("mov.b64 %0, {%1, %2};" : "=l"(r) : "f"(a), "f"(b));
    return r;
}

__global__ void __launch_bounds__(NTHREADS, 2)
fourier_elu_kernel(const ulonglong2* __restrict__ in, ulonglong2* __restrict__ out) {
    const int tid   = blockIdx.x * NTHREADS + threadIdx.x;   // 0 .. TOTAL4-1
    const int outer = tid >> 10;
    const int inner = tid & 1023;
    const int base  = outer * (8 * PLANE4) + inner;

    // Circulant kernel d[r], d[r]=d[7-r]; output mix e[s]=2*d[(s-1)&7].
    const float D0 =  0.31420871834f;
    const float D1 = -0.09353786017f;
    const float D2 =  0.04176116486f;
    const float D3 = -0.01243202296f;
    const u64 DD2[8] = { bc(D0), bc(D1), bc(D2), bc(D3),
                         bc(D3), bc(D2), bc(D1), bc(D0) };
    const u64 EE2[8] = { bc(2.0f*D0), bc(2.0f*D0), bc(2.0f*D1), bc(2.0f*D2),
                         bc(2.0f*D3), bc(2.0f*D3), bc(2.0f*D2), bc(2.0f*D1) };
    const u64 HALF   = bc(0.5f);
    const u64 NEG1   = bc(-1.0f);
    const u64 SC_P   = bc( 0.0625f);
    const u64 SC_N   = bc(-0.0625f);

    // Load 8 group samples as 2 packed f32x2 halves each (one LDG.128 per group).
    u64 xa[8], xb[8];
#pragma unroll
    for (int g = 0; g < 8; g++) {
        ulonglong2 v = in[base + g * PLANE4];
        xa[g] = v.x;
        xb[g] = v.y;
    }

    // Alternating sum (Nyquist bin contribution).
    u64 altA = xa[0], altB = xb[0];
#pragma unroll
    for (int n = 1; n < 8; n++) {
        if (n & 1) { altA = f2fma(xa[n], NEG1, altA); altB = f2fma(xb[n], NEG1, altB); }
        else       { altA = f2add(altA, xa[n]);       altB = f2add(altB, xb[n]); }
    }
    const u64 apA = f2mul(altA, SC_P), apB = f2mul(altB, SC_P);
    const u64 anA = f2mul(altA, SC_N), anB = f2mul(altB, SC_N);

    // y[m] accumulators: identity path = elu(even upsample).
    u64 accA[8], accB[8];
#pragma unroll
    for (int m = 0; m < 8; m++) {
        accA[m] = elu2(f2fma(xa[m], HALF, (m & 1) ? anA : apA));
        accB[m] = elu2(f2fma(xb[m], HALF, (m & 1) ? anB : apB));
    }

    // Odd upsamples: circulant, elu, scatter through e[].
#pragma unroll
    for (int t = 0; t < 8; t++) {
        u64 sA = f2mul(DD2[t & 7], xa[0]);
        u64 sB = f2mul(DD2[t & 7], xb[0]);
#pragma unroll
        for (int n = 1; n < 8; n++) {
            sA = f2fma(DD2[(t - n) & 7], xa[n], sA);
            sB = f2fma(DD2[(t - n) & 7], xb[n], sB);
        }
        sA = elu2(sA);
        sB = elu2(sB);
#pragma unroll
        for (int m = 0; m < 8; m++) {
            accA[m] = f2fma(EE2[(m - t) & 7], sA, accA[m]);
            accB[m] = f2fma(EE2[(m - t) & 7], sB, accB[m]);
        }
    }

#pragma unroll
    for (int g = 0; g < 8; g++) {
        ulonglong2 v;
        v.x = accA[g];
        v.y = accB[g];
        out[base + g * PLANE4] = v;
    }
}

extern "C" void kernel_launch(void* const* d_in, const int* in_sizes, int n_in,
                              void* d_out, int out_size) {
    (void)in_sizes; (void)n_in; (void)out_size;
    const ulonglong2* in2 = reinterpret_cast<const ulonglong2*>(d_in[0]);
    ulonglong2*       o2  = reinterpret_cast<ulonglong2*>(d_out);
    fourier_elu_kernel<<<TOTAL4 / NTHREADS, NTHREADS>>>(in2, o2);
}

// round 3
// speedup vs baseline: 1.1826x; 1.1245x over previous
#include <cuda_runtime.h>

// FourierELU on x[32,64,8,64,64], axis 2 (size 8):
//   rfft(8) -> pad to 9 bins -> irfft(16) -> elu -> rfft(16) -> keep 5 -> irfft(8)
// Closed form: y = B * elu(A * x):
//   alt        = sum_n (-1)^n x[n]
//   xup[2m]    = 0.5*x[m] + (-1)^m * alt/16
//   xup[2t+1]  = sum_n d[(t-n)&7] * x[n]          (8-pt symmetric circulant)
//   y[m]       = elu(xup[2m]) + sum_t e[(m-t)&7] * elu(xup[2t+1]), e[s]=2*d[(s-1)&7]
//
// R2: packed f32x2 (SASS FFMA2) for all linear chains.
// R3: 2 pixels/thread (one f32x2 per group sample) -> ~60 regs -> 4 CTAs/SM
//     for 2.3x occupancy and enough MLP to saturate HBM.

#define PLANE2  2048            // (64*64)/2 f32x2 per plane
#define OUTER   2048            // 32*64
#define TOTAL2  (OUTER * PLANE2)
#define NTHREADS 256

typedef unsigned long long u64;

__device__ __forceinline__ u64 bc(float f) {       // broadcast float into both f32x2 lanes
    unsigned u = __float_as_uint(f);
    return ((u64)u << 32) | (u64)u;
}

__device__ __forceinline__ u64 f2fma(u64 a, u64 b, u64 c) {
    u64 d;
    asm("fma.rn.f32x2 %0, %1, %2, %3;" : "=l"(d) : "l"(a), "l"(b), "l"(c));
    return d;
}
__device__ __forceinline__ u64 f2mul(u64 a, u64 b) {
    u64 d;
    asm("mul.rn.f32x2 %0, %1, %2;" : "=l"(d) : "l"(a), "l"(b));
    return d;
}
__device__ __forceinline__ u64 f2add(u64 a, u64 b) {
    u64 d;
    asm("add.rn.f32x2 %0, %1, %2;" : "=l"(d) : "l"(a), "l"(b));
    return d;
}

__device__ __forceinline__ float eluf(float v) {
    return v > 0.0f ? v : (__expf(v) - 1.0f);
}

__device__ __forceinline__ u64 elu2(u64 v) {
    float a, b;
    asm("mov.b64 {%0, %1}, %2;" : "=f"(a), "=f"(b) : "l"(v));
    a = eluf(a);
    b = eluf(b);
    u64 r;
    asm("mov.b64 %0, {%1, %2};" : "=l"(r) : "f"(a), "f"(b));
    return r;
}

__global__ void __launch_bounds__(NTHREADS, 4)
fourier_elu_kernel(const u64* __restrict__ in, u64* __restrict__ out) {
    const int tid   = blockIdx.x * NTHREADS + threadIdx.x;   // 0 .. TOTAL2-1
    const int outer = tid >> 11;          // (b,c) plane-group
    const int inner = tid & 2047;         // f32x2 index within 64x64 plane
    const int base  = outer * (8 * PLANE2) + inner;

    // Circulant kernel d[r], d[r]=d[7-r]; output mix e[s]=2*d[(s-1)&7].
    const float D0 =  0.31420871834f;
    const float D1 = -0.09353786017f;
    const float D2 =  0.04176116486f;
    const float D3 = -0.01243202296f;
    const u64 DD2[8] = { bc(D0), bc(D1), bc(D2), bc(D3),
                         bc(D3), bc(D2), bc(D1), bc(D0) };
    const u64 EE2[8] = { bc(2.0f*D0), bc(2.0f*D0), bc(2.0f*D1), bc(2.0f*D2),
                         bc(2.0f*D3), bc(2.0f*D3), bc(2.0f*D2), bc(2.0f*D1) };
    const u64 HALF   = bc(0.5f);
    const u64 NEG1   = bc(-1.0f);
    const u64 SC_P   = bc( 0.0625f);
    const u64 SC_N   = bc(-0.0625f);

    // Load 8 group samples (one f32x2 each), coalesced LDG.64.
    u64 x[8];
#pragma unroll
    for (int g = 0; g < 8; g++) {
        x[g] = in[base + g * PLANE2];
    }

    // Alternating sum (Nyquist bin contribution).
    u64 alt = x[0];
#pragma unroll
    for (int n = 1; n < 8; n++) {
        if (n & 1) alt = f2fma(x[n], NEG1, alt);
        else       alt = f2add(alt, x[n]);
    }
    const u64 ap = f2mul(alt, SC_P);
    const u64 an = f2mul(alt, SC_N);

    // y[m] accumulators: identity path = elu(even upsample).
    u64 acc[8];
#pragma unroll
    for (int m = 0; m < 8; m++) {
        acc[m] = elu2(f2fma(x[m], HALF, (m & 1) ? an : ap));
    }

    // Odd upsamples: circulant, elu, scatter through e[].
#pragma unroll
    for (int t = 0; t < 8; t++) {
        u64 s = f2mul(DD2[t & 7], x[0]);
#pragma unroll
        for (int n = 1; n < 8; n++) {
            s = f2fma(DD2[(t - n) & 7], x[n], s);
        }
        s = elu2(s);
#pragma unroll
        for (int m = 0; m < 8; m++) {
            acc[m] = f2fma(EE2[(m - t) & 7], s, acc[m]);
        }
    }

#pragma unroll
    for (int g = 0; g < 8; g++) {
        out[base + g * PLANE2] = acc[g];
    }
}

extern "C" void kernel_launch(void* const* d_in, const int* in_sizes, int n_in,
                              void* d_out, int out_size) {
    (void)in_sizes; (void)n_in; (void)out_size;
    const u64* in2 = reinterpret_cast<const u64*>(d_in[0]);
    u64*       o2  = reinterpret_cast<u64*>(d_out);
    fourier_elu_kernel<<<TOTAL2 / NTHREADS, NTHREADS>>>(in2, o2);
}

// round 4
// speedup vs baseline: 1.1900x; 1.0063x over previous
#include <cuda_runtime.h>

// FourierELU on x[32,64,8,64,64], axis 2 (size 8):
//   rfft(8) -> pad to 9 bins -> irfft(16) -> elu -> rfft(16) -> keep 5 -> irfft(8)
// Closed form: y = B * elu(A * x):
//   alt        = sum_n (-1)^n x[n]
//   xup[2m]    = 0.5*x[m] + (-1)^m * alt/16
//   xup[2t+1]  = sum_n d[(t-n)&7] * x[n]          (8-pt symmetric circulant)
//   y[m]       = elu(xup[2m]) + sum_t e[(m-t)&7] * elu(xup[2t+1]), e[s]=2*d[(s-1)&7]
//
// R2: packed f32x2 (SASS FFMA2) for all linear chains.
// R3: 2 pixels/thread, higher occupancy.
// R4: symmetry pair-sum factorization of both circulants (d[r]=d[7-r],
//     e[s]=e[(1-s)&7]): t/t+4 share pair sums of x, m/m+4 share pair sums of
//     elu(s). ~22% fewer fma-pipe ops. Gather form removes acc[] registers;
//     128-thr blocks with 9 CTAs/SM for 36 warps.

#define PLANE2  2048            // (64*64)/2 f32x2 per plane
#define OUTER   2048            // 32*64
#define TOTAL2  (OUTER * PLANE2)
#define NTHREADS 128

typedef unsigned long long u64;

__device__ __forceinline__ u64 bc(float f) {
    unsigned u = __float_as_uint(f);
    return ((u64)u << 32) | (u64)u;
}

__device__ __forceinline__ u64 f2fma(u64 a, u64 b, u64 c) {
    u64 d;
    asm("fma.rn.f32x2 %0, %1, %2, %3;" : "=l"(d) : "l"(a), "l"(b), "l"(c));
    return d;
}
__device__ __forceinline__ u64 f2mul(u64 a, u64 b) {
    u64 d;
    asm("mul.rn.f32x2 %0, %1, %2;" : "=l"(d) : "l"(a), "l"(b));
    return d;
}
__device__ __forceinline__ u64 f2add(u64 a, u64 b) {
    u64 d;
    asm("add.rn.f32x2 %0, %1, %2;" : "=l"(d) : "l"(a), "l"(b));
    return d;
}

__device__ __forceinline__ float eluf(float v) {
    return v > 0.0f ? v : (__expf(v) - 1.0f);
}

__device__ __forceinline__ u64 elu2(u64 v) {
    float a, b;
    asm("mov.b64 {%0, %1}, %2;" : "=f"(a), "=f"(b) : "l"(v));
    a = eluf(a);
    b = eluf(b);
    u64 r;
    asm("mov.b64 %0, {%1, %2};" : "=l"(r) : "f"(a), "f"(b));
    return r;
}

__global__ void __launch_bounds__(NTHREADS, 9)
fourier_elu_kernel(const u64* __restrict__ in, u64* __restrict__ out) {
    const int tid   = blockIdx.x * NTHREADS + threadIdx.x;   // 0 .. TOTAL2-1
    const int outer = tid >> 11;
    const int inner = tid & 2047;
    const int base  = outer * (8 * PLANE2) + inner;

    const float D0 =  0.31420871834f;
    const float D1 = -0.09353786017f;
    const float D2 =  0.04176116486f;
    const float D3 = -0.01243202296f;
    const u64 CD0 = bc(D0), CD1 = bc(D1), CD2 = bc(D2), CD3 = bc(D3);
    const u64 CE0 = bc(2.0f*D0), CE1 = bc(2.0f*D1),
              CE2 = bc(2.0f*D2), CE3 = bc(2.0f*D3);
    const u64 HALF = bc(0.5f);
    const u64 NEG1 = bc(-1.0f);
    const u64 SC_P = bc( 0.0625f);
    const u64 SC_N = bc(-0.0625f);

    // Load 8 group samples (one f32x2 each), coalesced LDG.64, front-batched.
    u64 x[8];
#pragma unroll
    for (int g = 0; g < 8; g++) {
        x[g] = in[base + g * PLANE2];
    }

    // Alternating sum (Nyquist bin contribution).
    u64 alt = x[0];
#pragma unroll
    for (int n = 1; n < 8; n++) {
        if (n & 1) alt = f2fma(x[n], NEG1, alt);
        else       alt = f2add(alt, x[n]);
    }
    const u64 ap = f2mul(alt, SC_P);
    const u64 an = f2mul(alt, SC_N);

    // Odd upsamples via symmetric circulant; t and t+4 share pair sums
    // P_j = x[n] + x[n'] with n + n' == 2t+1 (mod 8).
    u64 s[8];
#pragma unroll
    for (int t = 0; t < 4; t++) {
        u64 P0 = f2add(x[t],         x[(t + 1) & 7]);
        u64 P1 = f2add(x[(t + 7) & 7], x[(t + 2) & 7]);
        u64 P2 = f2add(x[(t + 6) & 7], x[(t + 3) & 7]);
        u64 P3 = f2add(x[(t + 5) & 7], x[(t + 4) & 7]);
        u64 a = f2mul(CD0, P0);
        a = f2fma(CD1, P1, a);
        a = f2fma(CD2, P2, a);
        a = f2fma(CD3, P3, a);
        u64 b = f2mul(CD3, P0);
        b = f2fma(CD2, P1, b);
        b = f2fma(CD1, P2, b);
        b = f2fma(CD0, P3, b);
        s[t]     = elu2(a);
        s[t + 4] = elu2(b);
    }

    // Gather outputs; m and m+4 share pair sums R_j of elu'd odd samples
    // (e[s] = e[(1-s)&7]). Even-upsample identity path folded in as the
    // accumulator seed. Store immediately (no acc array).
#pragma unroll
    for (int m = 0; m < 4; m++) {
        u64 R0 = f2add(s[m],           s[(m + 7) & 7]);
        u64 R1 = f2add(s[(m + 6) & 7], s[(m + 1) & 7]);
        u64 R2 = f2add(s[(m + 5) & 7], s[(m + 2) & 7]);
        u64 R3 = f2add(s[(m + 4) & 7], s[(m + 3) & 7]);

        u64 e0 = elu2(f2fma(x[m],     HALF, (m & 1) ? an : ap));
        u64 e4 = elu2(f2fma(x[m + 4], HALF, (m & 1) ? an : ap));

        u64 y0 = f2fma(CE0, R0, e0);
        y0 = f2fma(CE1, R1, y0);
        y0 = f2fma(CE2, R2, y0);
        y0 = f2fma(CE3, R3, y0);

        u64 y4 = f2fma(CE3, R0, e4);
        y4 = f2fma(CE2, R1, y4);
        y4 = f2fma(CE1, R2, y4);
        y4 = f2fma(CE0, R3, y4);

        out[base + m * PLANE2]       = y0;
        out[base + (m + 4) * PLANE2] = y4;
    }
}

extern "C" void kernel_launch(void* const* d_in, const int* in_sizes, int n_in,
                              void* d_out, int out_size) {
    (void)in_sizes; (void)n_in; (void)out_size;
    const u64* in2 = reinterpret_cast<const u64*>(d_in[0]);
    u64*       o2  = reinterpret_cast<u64*>(d_out);
    fourier_elu_kernel<<<TOTAL2 / NTHREADS, NTHREADS>>>(in2, o2);
}